// round 2
// baseline (speedup 1.0000x reference)
#include <cuda_runtime.h>

// KDE Gaussian: samples (B=2, S=4096, 2), locations (m=8192, 2)
// out[m,b] = sum_s exp(-|s-l|^2/(2 bw^2));  pdf[m,b] = out[m,b] / sum_m out[m,b]
//
// Exponent expansion with the per-location term kept INSIDE ex2 (range safety):
//   e = q + P + lx*Sx + ly*Sy = -k*dist^2 <= 0
//   q = -k|l|^2 (per thread), P = -k|s|^2, Sx = 2k*sx, Sy = 2k*sy (per sample, smem)
// Per pair: 2 FFMA + 1 FADD + 1 EX2 + 1 FADD(acc) -> fma pipe 8 cyc/warp, MUFU 8 cyc.

#define S_TOT   4096
#define M_TOT   8192
#define B_TOT   2
#define NSPLIT  8
#define CHUNK   (S_TOT / NSPLIT)   // 512
#define TPB     256

// k = log2(e) / (2 * bw^2),  bw = 0.2
#define KLOG    18.033688f

__device__ float g_partial[NSPLIT * B_TOT * M_TOT];   // [chunk][b][m]

__device__ __forceinline__ float ex2(float x) {
    float r;
    asm("ex2.approx.ftz.f32 %0, %1;" : "=f"(r) : "f"(x));
    return r;
}

__global__ __launch_bounds__(TPB)
void kde_partial_kernel(const float* __restrict__ samples,
                        const float* __restrict__ locs) {
    __shared__ float4 sh[CHUNK];

    const int bc    = blockIdx.y;      // 0..15
    const int b     = bc >> 3;         // batch index
    const int chunk = bc & 7;          // S-chunk index

    const float2* sp = reinterpret_cast<const float2*>(samples) + (b * S_TOT + chunk * CHUNK);
    for (int i = threadIdx.x; i < CHUNK; i += TPB) {
        float2 s = sp[i];
        sh[i] = make_float4(2.0f * KLOG * s.x,
                            2.0f * KLOG * s.y,
                            -KLOG * (s.x * s.x + s.y * s.y),
                            0.0f);
    }
    __syncthreads();

    const int m = blockIdx.x * TPB + threadIdx.x;   // 32*256 == 8192 exactly
    const float2 L = reinterpret_cast<const float2*>(locs)[m];
    const float q = -KLOG * (L.x * L.x + L.y * L.y);

    float a0 = 0.f, a1 = 0.f, a2 = 0.f, a3 = 0.f;
    #pragma unroll 4
    for (int i = 0; i < CHUNK; i += 4) {
        float4 s0 = sh[i + 0];
        float4 s1 = sh[i + 1];
        float4 s2 = sh[i + 2];
        float4 s3 = sh[i + 3];
        // e = q + P + Lx*Sx + Ly*Sy  (always <= 0; underflow flushes to 0, fine)
        a0 += ex2(q + fmaf(L.y, s0.y, fmaf(L.x, s0.x, s0.z)));
        a1 += ex2(q + fmaf(L.y, s1.y, fmaf(L.x, s1.x, s1.z)));
        a2 += ex2(q + fmaf(L.y, s2.y, fmaf(L.x, s2.x, s2.z)));
        a3 += ex2(q + fmaf(L.y, s3.y, fmaf(L.x, s3.x, s3.z)));
    }

    g_partial[(chunk * B_TOT + b) * M_TOT + m] = ((a0 + a1) + (a2 + a3));
}

// Finalize: one block per batch b. Reduce NSPLIT partials per m, compute the
// norm over all m within the block, write pdf = v/norm.
__global__ __launch_bounds__(1024)
void kde_finalize_kernel(float* __restrict__ out) {
    __shared__ float warp_red[32];
    const int b   = blockIdx.x;        // 0..1
    const int tid = threadIdx.x;       // 0..1023

    float v[8];
    float local = 0.f;
    #pragma unroll
    for (int j = 0; j < 8; j++) {
        const int m = j * 1024 + tid;
        float s = 0.f;
        #pragma unroll
        for (int c = 0; c < NSPLIT; c++)
            s += g_partial[(c * B_TOT + b) * M_TOT + m];
        v[j] = s;
        local += s;
    }

    // block reduction of `local` -> norm
    #pragma unroll
    for (int off = 16; off > 0; off >>= 1)
        local += __shfl_xor_sync(0xFFFFFFFFu, local, off);
    if ((tid & 31) == 0) warp_red[tid >> 5] = local;
    __syncthreads();
    if (tid < 32) {
        float w = warp_red[tid];
        #pragma unroll
        for (int off = 16; off > 0; off >>= 1)
            w += __shfl_xor_sync(0xFFFFFFFFu, w, off);
        if (tid == 0) warp_red[0] = w;
    }
    __syncthreads();
    const float inv_norm = 1.0f / warp_red[0];

    #pragma unroll
    for (int j = 0; j < 8; j++) {
        const int m = j * 1024 + tid;
        out[m * B_TOT + b] = v[j] * inv_norm;
    }
}

extern "C" void kernel_launch(void* const* d_in, const int* in_sizes, int n_in,
                              void* d_out, int out_size) {
    const float* samples = (const float*)d_in[0];   // (2, 4096, 2) f32
    const float* locs    = (const float*)d_in[1];   // (8192, 2)  f32
    float* out = (float*)d_out;                     // (1, 8192, 2) f32

    dim3 g1(M_TOT / TPB, NSPLIT * B_TOT);           // (32, 16)
    kde_partial_kernel<<<g1, TPB>>>(samples, locs);
    kde_finalize_kernel<<<B_TOT, 1024>>>(out);
}

// round 3
// speedup vs baseline: 1.2221x; 1.2221x over previous
#include <cuda_runtime.h>

// KDE Gaussian: samples (B=2, S=4096, 2), locations (m=8192, 2)
// out[m,b] = sum_s exp(-|s-l|^2/(2 bw^2));  pdf[m,b] = out[m,b] / sum_m out[m,b]
//
// e = q + P + Lx*Sx + Ly*Sy = -k*dist^2 <= 0   (range-safe)
// Packed f32x2 math: 2 samples per FMA-pipe op -> MUFU (EX2, 8 cyc/warp) is the
// sole bottleneck: ~28K cycles ~ 15us for the main kernel.

#define S_TOT   4096
#define M_TOT   8192
#define B_TOT   2
#define NSPLIT  16
#define CHUNK   (S_TOT / NSPLIT)   // 256
#define TPB     256
#define MTILES  (M_TOT / TPB)      // 32

#define KLOG    18.033688f         // log2(e) / (2*bw^2), bw=0.2

__device__ float g_partial[NSPLIT * B_TOT * M_TOT];  // [chunk][b][m]  (1 MB)
__device__ float g_bsum[NSPLIT * B_TOT * MTILES];    // [y][x] = 1024 block sums
__device__ float g_inv[B_TOT];

typedef unsigned long long u64;

__device__ __forceinline__ float ex2(float x) {
    float r; asm("ex2.approx.ftz.f32 %0, %1;" : "=f"(r) : "f"(x)); return r;
}
__device__ __forceinline__ u64 pack2(float lo, float hi) {
    u64 r; asm("mov.b64 %0, {%1, %2};" : "=l"(r) : "f"(lo), "f"(hi)); return r;
}
__device__ __forceinline__ void unpack2(u64 v, float& lo, float& hi) {
    asm("mov.b64 {%0, %1}, %2;" : "=f"(lo), "=f"(hi) : "l"(v));
}
__device__ __forceinline__ u64 fma2(u64 a, u64 b, u64 c) {
    u64 d; asm("fma.rn.f32x2 %0, %1, %2, %3;" : "=l"(d) : "l"(a), "l"(b), "l"(c)); return d;
}
__device__ __forceinline__ u64 add2(u64 a, u64 b) {
    u64 d; asm("add.rn.f32x2 %0, %1, %2;" : "=l"(d) : "l"(a), "l"(b)); return d;
}

__global__ __launch_bounds__(TPB)
void kde_partial_kernel(const float* __restrict__ samples,
                        const float* __restrict__ locs) {
    // per 2 samples: [Sx0,Sx1,Sy0,Sy1] (LDS.128) and [P0,P1] (LDS.64)
    __shared__ ulonglong2 shXY[CHUNK / 2];
    __shared__ u64        shP [CHUNK / 2];
    __shared__ float      wred[TPB / 32];

    const int y     = blockIdx.y;      // 0..31
    const int b     = y >> 4;
    const int chunk = y & 15;
    const int tid   = threadIdx.x;

    // preprocess 2 samples per thread (threads 0..127)
    if (tid < CHUNK / 2) {
        const float4 s2 = reinterpret_cast<const float4*>(samples)
                              [(b * S_TOT + chunk * CHUNK) / 2 + tid];
        // s2 = (sx0, sy0, sx1, sy1)
        float4 xy = make_float4(2.0f * KLOG * s2.x, 2.0f * KLOG * s2.z,
                                2.0f * KLOG * s2.y, 2.0f * KLOG * s2.w);
        *reinterpret_cast<float4*>(&shXY[tid]) = xy;
        shP[tid] = pack2(-KLOG * (s2.x * s2.x + s2.y * s2.y),
                         -KLOG * (s2.z * s2.z + s2.w * s2.w));
    }
    __syncthreads();

    const int m = blockIdx.x * TPB + tid;
    const float2 L = reinterpret_cast<const float2*>(locs)[m];
    const float q = -KLOG * (L.x * L.x + L.y * L.y);
    const u64 Lxx = pack2(L.x, L.x);
    const u64 Lyy = pack2(L.y, L.y);
    const u64 qq  = pack2(q, q);

    u64 acc0 = 0, acc1 = 0;   // bit-pattern {0.f,0.f}
    #pragma unroll 4
    for (int i = 0; i < CHUNK / 2; i += 2) {
        ulonglong2 xy0 = shXY[i];
        ulonglong2 xy1 = shXY[i + 1];
        u64 p0 = shP[i];
        u64 p1 = shP[i + 1];
        u64 e0 = add2(fma2(Lyy, xy0.y, fma2(Lxx, xy0.x, p0)), qq);
        u64 e1 = add2(fma2(Lyy, xy1.y, fma2(Lxx, xy1.x, p1)), qq);
        float a, bb, c, d;
        unpack2(e0, a, bb);
        unpack2(e1, c, d);
        acc0 = add2(acc0, pack2(ex2(a), ex2(bb)));
        acc1 = add2(acc1, pack2(ex2(c), ex2(d)));
    }

    float r0, r1, r2, r3;
    unpack2(acc0, r0, r1);
    unpack2(acc1, r2, r3);
    float v = (r0 + r1) + (r2 + r3);

    g_partial[(chunk * B_TOT + b) * M_TOT + m] = v;

    // block sum for the norm
    float w = v;
    #pragma unroll
    for (int off = 16; off > 0; off >>= 1)
        w += __shfl_xor_sync(0xFFFFFFFFu, w, off);
    if ((tid & 31) == 0) wred[tid >> 5] = w;
    __syncthreads();
    if (tid == 0) {
        float s = 0.f;
        #pragma unroll
        for (int j = 0; j < TPB / 32; j++) s += wred[j];
        g_bsum[y * MTILES + blockIdx.x] = s;
    }
}

// Sum the 1024 block sums into per-batch norms (1 block).
__global__ __launch_bounds__(1024)
void kde_norm_kernel() {
    __shared__ float wsum[32];
    const int tid = threadIdx.x;
    float v = g_bsum[tid];                  // tid<512 -> b=0, else b=1
    #pragma unroll
    for (int off = 16; off > 0; off >>= 1)
        v += __shfl_xor_sync(0xFFFFFFFFu, v, off);
    if ((tid & 31) == 0) wsum[tid >> 5] = v;
    __syncthreads();
    if (tid < B_TOT) {
        float s = 0.f;
        #pragma unroll
        for (int j = 0; j < 16; j++) s += wsum[tid * 16 + j];
        g_inv[tid] = 1.0f / s;
    }
}

// Reduce NSPLIT chunk partials per (m,b), scale by 1/norm, write pdf.
__global__ __launch_bounds__(256)
void kde_scale_kernel(float* __restrict__ out) {
    const int g = blockIdx.x * 256 + threadIdx.x;  // 0..16383
    const int b = g >> 13;
    const int m = g & (M_TOT - 1);
    float s = 0.f;
    #pragma unroll
    for (int c = 0; c < NSPLIT; c++)
        s += g_partial[(c * B_TOT + b) * M_TOT + m];
    out[m * B_TOT + b] = s * g_inv[b];
}

extern "C" void kernel_launch(void* const* d_in, const int* in_sizes, int n_in,
                              void* d_out, int out_size) {
    const float* samples = (const float*)d_in[0];   // (2, 4096, 2) f32
    const float* locs    = (const float*)d_in[1];   // (8192, 2)  f32
    float* out = (float*)d_out;                     // (1, 8192, 2) f32

    dim3 g1(MTILES, NSPLIT * B_TOT);                // (32, 32)
    kde_partial_kernel<<<g1, TPB>>>(samples, locs);
    kde_norm_kernel<<<1, 1024>>>();
    kde_scale_kernel<<<(M_TOT * B_TOT) / 256, 256>>>(out);
}